// round 16
// baseline (speedup 1.0000x reference)
#include <cuda_runtime.h>
#include <cuda_bf16.h>
#include <cstdint>

// Problem constants
#define BATCH 2
#define SEQ   2048
#define CDIM  1024
#define NHEAD 16
#define HD    64
#define C3    3072
#define MROWS (BATCH * SEQ)   // 4096

// ---------------- scratch (device globals; no allocation allowed) -----------
// bf16 split-precision operand scratch
__device__ __nv_bfloat16 g_ahi[MROWS * CDIM];
__device__ __nv_bfloat16 g_alo[MROWS * CDIM];
__device__ __nv_bfloat16 g_w1hi[C3 * CDIM];
__device__ __nv_bfloat16 g_w1lo[C3 * CDIM];
__device__ __nv_bfloat16 g_w2hi[CDIM * CDIM];
__device__ __nv_bfloat16 g_w2lo[CDIM * CDIM];

// attention operands, [B,H,T,hd] bf16 hi/lo
#define QKV_ELEMS (BATCH * NHEAD * SEQ * HD)
__device__ __nv_bfloat16 g_qhi[QKV_ELEMS];
__device__ __nv_bfloat16 g_qlo[QKV_ELEMS];
__device__ __nv_bfloat16 g_khi[QKV_ELEMS];
__device__ __nv_bfloat16 g_klo[QKV_ELEMS];
__device__ __nv_bfloat16 g_vhi[QKV_ELEMS];
__device__ __nv_bfloat16 g_vlo[QKV_ELEMS];

// ================= PTX helpers (plain sm_80+ PTX only) =======================
__device__ __forceinline__ uint32_t smem_u32(const void* p) {
    uint32_t a;
    asm("{ .reg .u64 tmp; cvta.to.shared.u64 tmp, %1; cvt.u32.u64 %0, tmp; }"
        : "=r"(a) : "l"(p));
    return a;
}
__device__ __forceinline__ void cp16(uint32_t s, const void* g) {
    asm volatile("cp.async.cg.shared.global [%0], [%1], 16;" :: "r"(s), "l"(g));
}
#define CP_COMMIT()  asm volatile("cp.async.commit_group;" ::: "memory")
#define CP_WAIT_1()  asm volatile("cp.async.wait_group 1;" ::: "memory")
#define CP_WAIT_0()  asm volatile("cp.async.wait_group 0;" ::: "memory")

#define LDM_X4(r, addr) \
    asm volatile("ldmatrix.sync.aligned.m8n8.x4.shared.b16 {%0,%1,%2,%3}, [%4];" \
                 : "=r"((r)[0]), "=r"((r)[1]), "=r"((r)[2]), "=r"((r)[3]) : "r"(addr))

#define LDM_X4_T(r, addr) \
    asm volatile("ldmatrix.sync.aligned.m8n8.x4.trans.shared.b16 {%0,%1,%2,%3}, [%4];" \
                 : "=r"((r)[0]), "=r"((r)[1]), "=r"((r)[2]), "=r"((r)[3]) : "r"(addr))

#define MMA16816(c, a, b0, b1) \
    asm volatile("mma.sync.aligned.m16n8k16.row.col.f32.bf16.bf16.f32 " \
                 "{%0,%1,%2,%3}, {%4,%5,%6,%7}, {%8,%9}, {%0,%1,%2,%3};" \
                 : "+f"((c)[0]), "+f"((c)[1]), "+f"((c)[2]), "+f"((c)[3]) \
                 : "r"((a)[0]), "r"((a)[1]), "r"((a)[2]), "r"((a)[3]), \
                   "r"(b0), "r"(b1))

// split pair of floats into hi/lo bf16x2 regs (lo halfword = first element)
__device__ __forceinline__ void split2(float p0, float p1, uint32_t& hi, uint32_t& lo) {
    __nv_bfloat16 h0 = __float2bfloat16(p0), h1 = __float2bfloat16(p1);
    __nv_bfloat162 hh; hh.x = h0; hh.y = h1;
    hi = *reinterpret_cast<uint32_t*>(&hh);
    __nv_bfloat162 ll;
    ll.x = __float2bfloat16(p0 - __bfloat162float(h0));
    ll.y = __float2bfloat16(p1 - __bfloat162float(h1));
    lo = *reinterpret_cast<uint32_t*>(&ll);
}

// ================= operand conversion kernels ================================
__global__ __launch_bounds__(256) void convert_split_kernel(
    int total4, const float4* __restrict__ src,
    __nv_bfloat162* __restrict__ hi, __nv_bfloat162* __restrict__ lo)
{
    int i = blockIdx.x * blockDim.x + threadIdx.x;
    if (i >= total4) return;
    float4 v = src[i];
    __nv_bfloat16 hx = __float2bfloat16(v.x), hy = __float2bfloat16(v.y);
    __nv_bfloat16 hz = __float2bfloat16(v.z), hw = __float2bfloat16(v.w);
    hi[2 * i]     = __nv_bfloat162(hx, hy);
    hi[2 * i + 1] = __nv_bfloat162(hz, hw);
    lo[2 * i]     = __nv_bfloat162(__float2bfloat16(v.x - __bfloat162float(hx)),
                                   __float2bfloat16(v.y - __bfloat162float(hy)));
    lo[2 * i + 1] = __nv_bfloat162(__float2bfloat16(v.z - __bfloat162float(hz)),
                                   __float2bfloat16(v.w - __bfloat162float(hw)));
}

__global__ __launch_bounds__(256) void transpose_split_kernel(
    int K, int N, const float* __restrict__ W,
    __nv_bfloat16* __restrict__ Thi, __nv_bfloat16* __restrict__ Tlo)
{
    __shared__ float t[32][33];
    const int n0 = blockIdx.x * 32, k0 = blockIdx.y * 32;
    const int tx = threadIdx.x, ty = threadIdx.y;   // 32 x 8
#pragma unroll
    for (int j = 0; j < 4; j++) {
        int k = k0 + ty + j * 8;
        t[ty + j * 8][tx] = W[(size_t)k * N + n0 + tx];
    }
    __syncthreads();
#pragma unroll
    for (int j = 0; j < 4; j++) {
        int n = n0 + ty + j * 8;
        int k = k0 + tx;
        float v = t[tx][ty + j * 8];
        __nv_bfloat16 h = __float2bfloat16(v);
        Thi[(size_t)n * K + k] = h;
        Tlo[(size_t)n * K + k] = __float2bfloat16(v - __bfloat162float(h));
    }
}

// ================= mma.sync GEMM: C[M,N] = A[M,K] @ Bt[N,K]^T + bias =========
// mode 0: write fp32 C.  mode 1: GEMM1 epilogue — apply head-indexed RoPE and
// write split-bf16 q/k/v directly ([B,H,T,hd] layout).
#define GBK   32
#define PSTR  40
#define PART_SM  (128 * PSTR * 2)
#define STAGE_SM (4 * PART_SM)
#define GEMM_SMEM (2 * STAGE_SM)

__global__ __launch_bounds__(256, 2) void gemm_mma_kernel(
    int K, int N,
    const __nv_bfloat16* __restrict__ Ahi, const __nv_bfloat16* __restrict__ Alo,
    const __nv_bfloat16* __restrict__ Bhi, const __nv_bfloat16* __restrict__ Blo,
    const float* __restrict__ bias, float* __restrict__ C,
    int mode,
    __nv_bfloat16* __restrict__ qhi, __nv_bfloat16* __restrict__ qlo,
    __nv_bfloat16* __restrict__ khi, __nv_bfloat16* __restrict__ klo,
    __nv_bfloat16* __restrict__ vhi, __nv_bfloat16* __restrict__ vlo)
{
    extern __shared__ char smem[];
    const uint32_t smb = smem_u32(smem);
    const int tid = threadIdx.x;
    const int lane = tid & 31;
    const int wid = tid >> 5;
    const int bx = blockIdx.x;
    const int by = blockIdx.y;
    const int wm = wid >> 1;
    const int wn = wid & 1;

    const __nv_bfloat16* src[4];
    src[0] = Ahi + (size_t)by * 128 * K;
    src[1] = Alo + (size_t)by * 128 * K;
    src[2] = Bhi + (size_t)bx * 128 * K;
    src[3] = Blo + (size_t)bx * 128 * K;

    const int lr = tid >> 1;
    const int lu = (tid & 1) * 2;

    float acc[2][8][4];
#pragma unroll
    for (int mt = 0; mt < 2; mt++)
#pragma unroll
        for (int nt = 0; nt < 8; nt++)
#pragma unroll
            for (int j = 0; j < 4; j++) acc[mt][nt][j] = 0.f;

    const int nch = K / GBK;
    {
        const uint32_t sb = smb;
#pragma unroll
        for (int p = 0; p < 4; p++) {
            const char* g = (const char*)(src[p] + (size_t)lr * K);
            uint32_t s = sb + p * PART_SM + lr * 80 + lu * 16;
            cp16(s,      g + lu * 16);
            cp16(s + 16, g + lu * 16 + 16);
        }
        CP_COMMIT();
    }

    for (int ch = 0; ch < nch; ch++) {
        if (ch + 1 < nch) {
            const uint32_t sb = smb + ((ch + 1) & 1) * STAGE_SM;
            const int koff = (ch + 1) * GBK;
#pragma unroll
            for (int p = 0; p < 4; p++) {
                const char* g = (const char*)(src[p] + (size_t)lr * K + koff);
                uint32_t s = sb + p * PART_SM + lr * 80 + lu * 16;
                cp16(s,      g + lu * 16);
                cp16(s + 16, g + lu * 16 + 16);
            }
            CP_COMMIT();
            CP_WAIT_1();
        } else {
            CP_WAIT_0();
        }
        __syncthreads();

        const uint32_t sb = smb + (ch & 1) * STAGE_SM;
#pragma unroll
        for (int ks = 0; ks < 2; ks++) {
            const int kb = ks * 16;
            uint32_t a[2][2][4];
#pragma unroll
            for (int pp = 0; pp < 2; pp++) {
#pragma unroll
                for (int mt = 0; mt < 2; mt++) {
                    int row = wm * 32 + mt * 16 + (lane & 15);
                    int kk  = kb + ((lane >> 4) & 1) * 8;
                    uint32_t ad = sb + pp * PART_SM + row * 80 + kk * 2;
                    LDM_X4(a[pp][mt], ad);
                }
            }
#pragma unroll
            for (int np = 0; np < 4; np++) {
                int rowb = wn * 64 + np * 16 + (lane & 7) + ((lane >> 4) & 1) * 8;
                int kk   = kb + ((lane >> 3) & 1) * 8;
                uint32_t bh[4], bl[4];
                LDM_X4(bh, sb + 2 * PART_SM + rowb * 80 + kk * 2);
                LDM_X4(bl, sb + 3 * PART_SM + rowb * 80 + kk * 2);
#pragma unroll
                for (int half = 0; half < 2; half++)
#pragma unroll
                    for (int mt = 0; mt < 2; mt++)
                        MMA16816(acc[mt][np * 2 + half], a[0][mt],
                                 bh[half * 2], bh[half * 2 + 1]);
#pragma unroll
                for (int half = 0; half < 2; half++)
#pragma unroll
                    for (int mt = 0; mt < 2; mt++)
                        MMA16816(acc[mt][np * 2 + half], a[0][mt],
                                 bl[half * 2], bl[half * 2 + 1]);
#pragma unroll
                for (int half = 0; half < 2; half++)
#pragma unroll
                    for (int mt = 0; mt < 2; mt++)
                        MMA16816(acc[mt][np * 2 + half], a[1][mt],
                                 bh[half * 2], bh[half * 2 + 1]);
            }
        }
        __syncthreads();
    }

    const int gq = lane >> 2;
    const int cn = (lane & 3) * 2;
    if (mode == 0) {
#pragma unroll
        for (int mt = 0; mt < 2; mt++) {
            const int row = by * 128 + wm * 32 + mt * 16 + gq;
#pragma unroll
            for (int nt = 0; nt < 8; nt++) {
                const int col = bx * 128 + wn * 64 + nt * 8 + cn;
                const float2 bb = *(const float2*)(bias + col);
                float2 o0, o1;
                o0.x = acc[mt][nt][0] + bb.x;
                o0.y = acc[mt][nt][1] + bb.y;
                o1.x = acc[mt][nt][2] + bb.x;
                o1.y = acc[mt][nt][3] + bb.y;
                *(float2*)(C + (size_t)row * N + col)       = o0;
                *(float2*)(C + (size_t)(row + 8) * N + col) = o1;
            }
        }
    } else {
        // RoPE + split epilogue (GEMM1). col pair (col, col+1) = rope pair.
#pragma unroll
        for (int nt = 0; nt < 8; nt++) {
            const int col = bx * 128 + wn * 64 + nt * 8 + cn;
            const int p3  = col >> 10;           // 0=q 1=k 2=v
            const int rem = col & 1023;
            const int hh  = rem >> 6;
            const int d   = rem & 63;
            float si = 0.f, co = 1.f;
            if (p3 < 2) {
                const float theta = __powf(10000.0f, -(float)(d >> 1) / 32.0f);
                sincosf((float)hh * theta, &si, &co);
            }
            const float b0 = bias[col], b1 = bias[col + 1];
            __nv_bfloat16* dsthi = (p3 == 0) ? qhi : (p3 == 1) ? khi : vhi;
            __nv_bfloat16* dstlo = (p3 == 0) ? qlo : (p3 == 1) ? klo : vlo;
#pragma unroll
            for (int mt = 0; mt < 2; mt++) {
#pragma unroll
                for (int rr = 0; rr < 2; rr++) {
                    const int mm = by * 128 + wm * 32 + mt * 16 + gq + rr * 8;
                    const int bb = mm >> 11;          // / SEQ
                    const int tt = mm & (SEQ - 1);
                    float v0 = acc[mt][nt][rr * 2 + 0] + b0;
                    float v1 = acc[mt][nt][rr * 2 + 1] + b1;
                    float o0, o1;
                    if (p3 < 2) {
                        o0 = v0 * co - v1 * si;
                        o1 = v1 * co + v0 * si;
                    } else {
                        o0 = v0; o1 = v1;
                    }
                    const size_t off =
                        (((size_t)(bb * NHEAD + hh)) * SEQ + tt) * HD + d;
                    uint32_t hi, lo;
                    split2(o0, o1, hi, lo);
                    *reinterpret_cast<uint32_t*>(dsthi + off) = hi;
                    *reinterpret_cast<uint32_t*>(dstlo + off) = lo;
                }
            }
        }
    }
}

// ---------------- Flash attention (causal), mma.sync bf16 split --------------
// CTA: 64 q rows (4 warps x m16), 128 threads -> 2 CTAs/SM for barrier overlap.
// K/V tiles 64 rows, double-buffered cp.async. Q staged in stage-0 area first.
#define AKSTRB 144
#define APART  (64 * AKSTRB)          // 9216
#define ASTAGE (4 * APART)            // 36864
#define ATTN_SMEM (2 * ASTAGE)        // 73728

__global__ __launch_bounds__(128, 2) void attn_mma_kernel(
    const __nv_bfloat16* __restrict__ Qhi, const __nv_bfloat16* __restrict__ Qlo,
    const __nv_bfloat16* __restrict__ Khi, const __nv_bfloat16* __restrict__ Klo,
    const __nv_bfloat16* __restrict__ Vhi, const __nv_bfloat16* __restrict__ Vlo,
    __nv_bfloat16* __restrict__ Yhi, __nv_bfloat16* __restrict__ Ylo)
{
    extern __shared__ char smem[];
    const uint32_t smb = smem_u32(smem);
    const int tid = threadIdx.x, lane = tid & 31, wid = tid >> 5;   // wid 0..3
    const int qt = blockIdx.x, h = blockIdx.y, b = blockIdx.z;
    const int qbase = qt * 64;
    const size_t headOff = ((size_t)(b * NHEAD + h)) * SEQ * HD;

    // ---- stage Q (hi then lo, 64 rows each) into stage-0 area ----
    {
        const int part = tid >> 6;       // 0..1
        const int row  = tid & 63;
        const __nv_bfloat16* gqp =
            (part == 0 ? Qhi : Qlo) + headOff + (size_t)(qbase + row) * HD;
        uint32_t s = smb + part * APART + row * AKSTRB;
#pragma unroll
        for (int u = 0; u < 8; u++) cp16(s + u * 16, (const char*)gqp + u * 16);
        CP_COMMIT();
        CP_WAIT_0();
    }
    __syncthreads();

    uint32_t qh[4][4], ql[4][4];
    {
        const int row = wid * 16 + (lane & 15);
        const int ko  = ((lane >> 4) & 1) * 8;
#pragma unroll
        for (int kb = 0; kb < 4; kb++) {
            uint32_t ad = smb + row * AKSTRB + (kb * 16 + ko) * 2;
            LDM_X4(qh[kb], ad);
            LDM_X4(ql[kb], ad + APART);
        }
    }
    __syncthreads();

    float m0 = -1e30f, m1 = -1e30f, l0 = 0.f, l1 = 0.f;
    float Oacc[8][4];
#pragma unroll
    for (int nt = 0; nt < 8; nt++)
#pragma unroll
        for (int j = 0; j < 4; j++) Oacc[nt][j] = 0.f;

    const int nkt = qt + 1;
    const int ldp = tid >> 5;        // 0..3: Khi,Klo,Vhi,Vlo (one warp each)
    const int ldr = tid & 31;
    const __nv_bfloat16* ldsrc =
        (ldp == 0 ? Khi : ldp == 1 ? Klo : ldp == 2 ? Vhi : Vlo) + headOff;

    // prologue: kt = 0 -> stage 0
    {
#pragma unroll
        for (int rr = 0; rr < 2; rr++) {
            const int row = ldr + rr * 32;
            const char* g = (const char*)(ldsrc + (size_t)row * HD);
            uint32_t s = smb + ldp * APART + row * AKSTRB;
#pragma unroll
            for (int u = 0; u < 8; u++) cp16(s + u * 16, g + u * 16);
        }
        CP_COMMIT();
    }

    const int gq = lane >> 2;
    const int c2 = (lane & 3) * 2;

    for (int kt = 0; kt < nkt; kt++) {
        if (kt + 1 < nkt) {
#pragma unroll
            for (int rr = 0; rr < 2; rr++) {
                const int row = ldr + rr * 32;
                const char* g = (const char*)(ldsrc + (size_t)((kt + 1) * 64 + row) * HD);
                uint32_t s = smb + ((kt + 1) & 1) * ASTAGE + ldp * APART + row * AKSTRB;
#pragma unroll
                for (int u = 0; u < 8; u++) cp16(s + u * 16, g + u * 16);
            }
            CP_COMMIT();
            CP_WAIT_1();
        } else {
            CP_WAIT_0();
        }
        __syncthreads();

        const uint32_t sb = smb + (kt & 1) * ASTAGE;
        const int ktbase = kt * 64;
        if (ktbase <= qbase + wid * 16 + 15) {
            float acc[8][4];
#pragma unroll
            for (int nt = 0; nt < 8; nt++)
#pragma unroll
                for (int j = 0; j < 4; j++) acc[nt][j] = 0.f;

            // ---- S = Q K^T, np in pairs for 4-wide RAW separation ----
#pragma unroll
            for (int kb = 0; kb < 4; kb++) {
                const int kcol = kb * 16 + ((lane >> 3) & 1) * 8;
#pragma unroll
                for (int npp = 0; npp < 2; npp++) {
                    const int nr0 = (npp * 2) * 16 + (lane & 7) + ((lane >> 4) & 1) * 8;
                    const int nr1 = (npp * 2 + 1) * 16 + (lane & 7) + ((lane >> 4) & 1) * 8;
                    uint32_t kh0[4], kl0[4], kh1[4], kl1[4];
                    const uint32_t ad0 = sb + nr0 * AKSTRB + kcol * 2;
                    const uint32_t ad1 = sb + nr1 * AKSTRB + kcol * 2;
                    LDM_X4(kh0, ad0);
                    LDM_X4(kl0, ad0 + APART);
                    LDM_X4(kh1, ad1);
                    LDM_X4(kl1, ad1 + APART);
                    const int t0 = npp * 4;
                    MMA16816(acc[t0 + 0], qh[kb], kh0[0], kh0[1]);
                    MMA16816(acc[t0 + 1], qh[kb], kh0[2], kh0[3]);
                    MMA16816(acc[t0 + 2], qh[kb], kh1[0], kh1[1]);
                    MMA16816(acc[t0 + 3], qh[kb], kh1[2], kh1[3]);
                    MMA16816(acc[t0 + 0], qh[kb], kl0[0], kl0[1]);
                    MMA16816(acc[t0 + 1], qh[kb], kl0[2], kl0[3]);
                    MMA16816(acc[t0 + 2], qh[kb], kl1[0], kl1[1]);
                    MMA16816(acc[t0 + 3], qh[kb], kl1[2], kl1[3]);
                    MMA16816(acc[t0 + 0], ql[kb], kh0[0], kh0[1]);
                    MMA16816(acc[t0 + 1], ql[kb], kh0[2], kh0[3]);
                    MMA16816(acc[t0 + 2], ql[kb], kh1[0], kh1[1]);
                    MMA16816(acc[t0 + 3], ql[kb], kh1[2], kh1[3]);
                }
            }

            const int row0 = qbase + wid * 16 + gq;
            const int row1 = row0 + 8;
            if (ktbase + 63 > qbase + wid * 16) {
#pragma unroll
                for (int nt = 0; nt < 8; nt++) {
#pragma unroll
                    for (int j = 0; j < 4; j++) {
                        const int col = ktbase + nt * 8 + c2 + (j & 1);
                        const int r   = (j < 2) ? row0 : row1;
                        float sv = acc[nt][j] * 0.125f;
                        if (col > r) sv = -1e30f;
                        acc[nt][j] = sv;
                    }
                }
            } else {
#pragma unroll
                for (int nt = 0; nt < 8; nt++)
#pragma unroll
                    for (int j = 0; j < 4; j++) acc[nt][j] *= 0.125f;
            }

            float mx0 = -1e30f, mx1 = -1e30f;
#pragma unroll
            for (int nt = 0; nt < 8; nt++) {
                mx0 = fmaxf(mx0, fmaxf(acc[nt][0], acc[nt][1]));
                mx1 = fmaxf(mx1, fmaxf(acc[nt][2], acc[nt][3]));
            }
            mx0 = fmaxf(mx0, __shfl_xor_sync(0xffffffffu, mx0, 1));
            mx0 = fmaxf(mx0, __shfl_xor_sync(0xffffffffu, mx0, 2));
            mx1 = fmaxf(mx1, __shfl_xor_sync(0xffffffffu, mx1, 1));
            mx1 = fmaxf(mx1, __shfl_xor_sync(0xffffffffu, mx1, 2));

            const float mn0 = fmaxf(m0, mx0), mn1 = fmaxf(m1, mx1);
            const float al0 = __expf(m0 - mn0), al1 = __expf(m1 - mn1);
            float s0 = 0.f, s1 = 0.f;
#pragma unroll
            for (int nt = 0; nt < 8; nt++) {
                float p0 = __expf(acc[nt][0] - mn0);
                float p1 = __expf(acc[nt][1] - mn0);
                float p2 = __expf(acc[nt][2] - mn1);
                float p3 = __expf(acc[nt][3] - mn1);
                acc[nt][0] = p0; acc[nt][1] = p1; acc[nt][2] = p2; acc[nt][3] = p3;
                s0 += p0 + p1;
                s1 += p2 + p3;
            }
            s0 += __shfl_xor_sync(0xffffffffu, s0, 1);
            s0 += __shfl_xor_sync(0xffffffffu, s0, 2);
            s1 += __shfl_xor_sync(0xffffffffu, s1, 1);
            s1 += __shfl_xor_sync(0xffffffffu, s1, 2);
            l0 = l0 * al0 + s0;
            l1 = l1 * al1 + s1;
            m0 = mn0; m1 = mn1;
#pragma unroll
            for (int nt = 0; nt < 8; nt++) {
                Oacc[nt][0] *= al0; Oacc[nt][1] *= al0;
                Oacc[nt][2] *= al1; Oacc[nt][3] *= al1;
            }

            // ---- O += P V, np pairs for 4-wide RAW separation ----
#pragma unroll
            for (int kb = 0; kb < 4; kb++) {
                uint32_t ph[4], pl[4];
                split2(acc[2 * kb][0],     acc[2 * kb][1],     ph[0], pl[0]);
                split2(acc[2 * kb][2],     acc[2 * kb][3],     ph[1], pl[1]);
                split2(acc[2 * kb + 1][0], acc[2 * kb + 1][1], ph[2], pl[2]);
                split2(acc[2 * kb + 1][2], acc[2 * kb + 1][3], ph[3], pl[3]);
                const int krow = kb * 16 + (lane & 7) + ((lane >> 3) & 1) * 8;
#pragma unroll
                for (int npp = 0; npp < 2; npp++) {
                    const int nc0 = (npp * 2) * 16 + ((lane >> 4) & 1) * 8;
                    const int nc1 = (npp * 2 + 1) * 16 + ((lane >> 4) & 1) * 8;
                    uint32_t vh0[4], vl0[4], vh1[4], vl1[4];
                    const uint32_t ad0 = sb + 2 * APART + krow * AKSTRB + nc0 * 2;
                    const uint32_t ad1 = sb + 2 * APART + krow * AKSTRB + nc1 * 2;
                    LDM_X4_T(vh0, ad0);
                    LDM_X4_T(vl0, ad0 + APART);
                    LDM_X4_T(vh1, ad1);
                    LDM_X4_T(vl1, ad1 + APART);
                    const int t0 = npp * 4;
                    MMA16816(Oacc[t0 + 0], ph, vh0[0], vh0[1]);
                    MMA16816(Oacc[t0 + 1], ph, vh0[2], vh0[3]);
                    MMA16816(Oacc[t0 + 2], ph, vh1[0], vh1[1]);
                    MMA16816(Oacc[t0 + 3], ph, vh1[2], vh1[3]);
                    MMA16816(Oacc[t0 + 0], ph, vl0[0], vl0[1]);
                    MMA16816(Oacc[t0 + 1], ph, vl0[2], vl0[3]);
                    MMA16816(Oacc[t0 + 2], ph, vl1[0], vl1[1]);
                    MMA16816(Oacc[t0 + 3], ph, vl1[2], vl1[3]);
                    MMA16816(Oacc[t0 + 0], pl, vh0[0], vh0[1]);
                    MMA16816(Oacc[t0 + 1], pl, vh0[2], vh0[3]);
                    MMA16816(Oacc[t0 + 2], pl, vh1[0], vh1[1]);
                    MMA16816(Oacc[t0 + 3], pl, vh1[2], vh1[3]);
                }
            }
        }
        __syncthreads();
    }

    // ---- epilogue: normalize, split to bf16 hi/lo, store into GEMM2 A-layout -
    const float inv0 = 1.0f / l0, inv1 = 1.0f / l1;
    const int r0 = qbase + wid * 16 + gq;
    const size_t m0r = (size_t)b * SEQ + r0;
    const size_t m1r = m0r + 8;
    const int colb = h * HD + c2;
#pragma unroll
    for (int nt = 0; nt < 8; nt++) {
        uint32_t hi0, lo0, hi1, lo1;
        split2(Oacc[nt][0] * inv0, Oacc[nt][1] * inv0, hi0, lo0);
        split2(Oacc[nt][2] * inv1, Oacc[nt][3] * inv1, hi1, lo1);
        const size_t o0 = m0r * CDIM + colb + nt * 8;
        const size_t o1 = m1r * CDIM + colb + nt * 8;
        *reinterpret_cast<uint32_t*>(Yhi + o0) = hi0;
        *reinterpret_cast<uint32_t*>(Ylo + o0) = lo0;
        *reinterpret_cast<uint32_t*>(Yhi + o1) = hi1;
        *reinterpret_cast<uint32_t*>(Ylo + o1) = lo1;
    }
}

// ---------------- launch ----------------------------------------------------
extern "C" void kernel_launch(void* const* d_in, const int* in_sizes, int n_in,
                              void* d_out, int out_size)
{
    const float* x      = (const float*)d_in[0];
    const float* W_attn = (const float*)d_in[1];
    const float* b_attn = (const float*)d_in[2];
    const float* W_proj = (const float*)d_in[3];
    const float* b_proj = (const float*)d_in[4];
    float* out = (float*)d_out;

    __nv_bfloat16 *ahi, *alo, *w1hi, *w1lo, *w2hi, *w2lo;
    __nv_bfloat16 *qhi, *qlo, *khi, *klo, *vhi, *vlo;
    cudaGetSymbolAddress((void**)&ahi,  g_ahi);
    cudaGetSymbolAddress((void**)&alo,  g_alo);
    cudaGetSymbolAddress((void**)&w1hi, g_w1hi);
    cudaGetSymbolAddress((void**)&w1lo, g_w1lo);
    cudaGetSymbolAddress((void**)&w2hi, g_w2hi);
    cudaGetSymbolAddress((void**)&w2lo, g_w2lo);
    cudaGetSymbolAddress((void**)&qhi,  g_qhi);
    cudaGetSymbolAddress((void**)&qlo,  g_qlo);
    cudaGetSymbolAddress((void**)&khi,  g_khi);
    cudaGetSymbolAddress((void**)&klo,  g_klo);
    cudaGetSymbolAddress((void**)&vhi,  g_vhi);
    cudaGetSymbolAddress((void**)&vlo,  g_vlo);

    cudaFuncSetAttribute(gemm_mma_kernel,
                         cudaFuncAttributeMaxDynamicSharedMemorySize, GEMM_SMEM);
    cudaFuncSetAttribute(attn_mma_kernel,
                         cudaFuncAttributeMaxDynamicSharedMemorySize, ATTN_SMEM);

    // convert weights (transpose + split)
    {
        dim3 blk(32, 8);
        dim3 g1(C3 / 32, CDIM / 32);
        transpose_split_kernel<<<g1, blk>>>(CDIM, C3, W_attn, w1hi, w1lo);
        dim3 g2(CDIM / 32, CDIM / 32);
        transpose_split_kernel<<<g2, blk>>>(CDIM, CDIM, W_proj, w2hi, w2lo);
    }
    // convert x
    {
        int total4 = MROWS * CDIM / 4;
        convert_split_kernel<<<(total4 + 255) / 256, 256>>>(
            total4, (const float4*)x, (__nv_bfloat162*)ahi, (__nv_bfloat162*)alo);
    }
    // GEMM1 (fused RoPE + split epilogue): q/k/v <- rope(x @ W_attn + b_attn)
    {
        dim3 grid(C3 / 128, MROWS / 128);
        gemm_mma_kernel<<<grid, 256, GEMM_SMEM>>>(CDIM, C3,
                                                  ahi, alo, w1hi, w1lo, b_attn,
                                                  nullptr, 1,
                                                  qhi, qlo, khi, klo, vhi, vlo);
    }
    // Flash attention (tensor cores), writes split-bf16 y directly
    {
        dim3 grid(SEQ / 64, NHEAD, BATCH);
        attn_mma_kernel<<<grid, 128, ATTN_SMEM>>>(qhi, qlo, khi, klo, vhi, vlo,
                                                  ahi, alo);
    }
    // GEMM2: out = y @ W_proj + b_proj
    {
        dim3 grid(CDIM / 128, MROWS / 128);
        gemm_mma_kernel<<<grid, 256, GEMM_SMEM>>>(CDIM, CDIM,
                                                  ahi, alo, w2hi, w2lo, b_proj,
                                                  out, 0,
                                                  nullptr, nullptr, nullptr,
                                                  nullptr, nullptr, nullptr);
    }
}

// round 17
// speedup vs baseline: 1.0524x; 1.0524x over previous
#include <cuda_runtime.h>
#include <cuda_bf16.h>
#include <cstdint>

// Problem constants
#define BATCH 2
#define SEQ   2048
#define CDIM  1024
#define NHEAD 16
#define HD    64
#define C3    3072
#define MROWS (BATCH * SEQ)   // 4096

// ---------------- scratch (device globals; no allocation allowed) -----------
__device__ __nv_bfloat16 g_ahi[MROWS * CDIM];
__device__ __nv_bfloat16 g_alo[MROWS * CDIM];
__device__ __nv_bfloat16 g_w1hi[C3 * CDIM];
__device__ __nv_bfloat16 g_w1lo[C3 * CDIM];
__device__ __nv_bfloat16 g_w2hi[CDIM * CDIM];
__device__ __nv_bfloat16 g_w2lo[CDIM * CDIM];

#define QKV_ELEMS (BATCH * NHEAD * SEQ * HD)
__device__ __nv_bfloat16 g_qhi[QKV_ELEMS];
__device__ __nv_bfloat16 g_qlo[QKV_ELEMS];
__device__ __nv_bfloat16 g_khi[QKV_ELEMS];
__device__ __nv_bfloat16 g_klo[QKV_ELEMS];
__device__ __nv_bfloat16 g_vhi[QKV_ELEMS];
__device__ __nv_bfloat16 g_vlo[QKV_ELEMS];

// ================= PTX helpers (plain sm_80+ PTX only) =======================
__device__ __forceinline__ uint32_t smem_u32(const void* p) {
    uint32_t a;
    asm("{ .reg .u64 tmp; cvta.to.shared.u64 tmp, %1; cvt.u32.u64 %0, tmp; }"
        : "=r"(a) : "l"(p));
    return a;
}
__device__ __forceinline__ void cp16(uint32_t s, const void* g) {
    asm volatile("cp.async.cg.shared.global [%0], [%1], 16;" :: "r"(s), "l"(g));
}
#define CP_COMMIT()  asm volatile("cp.async.commit_group;" ::: "memory")
#define CP_WAIT_1()  asm volatile("cp.async.wait_group 1;" ::: "memory")
#define CP_WAIT_0()  asm volatile("cp.async.wait_group 0;" ::: "memory")

#define LDM_X4(r, addr) \
    asm volatile("ldmatrix.sync.aligned.m8n8.x4.shared.b16 {%0,%1,%2,%3}, [%4];" \
                 : "=r"((r)[0]), "=r"((r)[1]), "=r"((r)[2]), "=r"((r)[3]) : "r"(addr))

#define LDM_X4_T(r, addr) \
    asm volatile("ldmatrix.sync.aligned.m8n8.x4.trans.shared.b16 {%0,%1,%2,%3}, [%4];" \
                 : "=r"((r)[0]), "=r"((r)[1]), "=r"((r)[2]), "=r"((r)[3]) : "r"(addr))

#define MMA16816(c, a, b0, b1) \
    asm volatile("mma.sync.aligned.m16n8k16.row.col.f32.bf16.bf16.f32 " \
                 "{%0,%1,%2,%3}, {%4,%5,%6,%7}, {%8,%9}, {%0,%1,%2,%3};" \
                 : "+f"((c)[0]), "+f"((c)[1]), "+f"((c)[2]), "+f"((c)[3]) \
                 : "r"((a)[0]), "r"((a)[1]), "r"((a)[2]), "r"((a)[3]), \
                   "r"(b0), "r"(b1))

__device__ __forceinline__ void split2(float p0, float p1, uint32_t& hi, uint32_t& lo) {
    __nv_bfloat16 h0 = __float2bfloat16(p0), h1 = __float2bfloat16(p1);
    __nv_bfloat162 hh; hh.x = h0; hh.y = h1;
    hi = *reinterpret_cast<uint32_t*>(&hh);
    __nv_bfloat162 ll;
    ll.x = __float2bfloat16(p0 - __bfloat162float(h0));
    ll.y = __float2bfloat16(p1 - __bfloat162float(h1));
    lo = *reinterpret_cast<uint32_t*>(&ll);
}

// ================= operand conversion kernels ================================
__global__ __launch_bounds__(256) void convert_split_kernel(
    int total4, const float4* __restrict__ src,
    __nv_bfloat162* __restrict__ hi, __nv_bfloat162* __restrict__ lo)
{
    int i = blockIdx.x * blockDim.x + threadIdx.x;
    if (i >= total4) return;
    float4 v = src[i];
    __nv_bfloat16 hx = __float2bfloat16(v.x), hy = __float2bfloat16(v.y);
    __nv_bfloat16 hz = __float2bfloat16(v.z), hw = __float2bfloat16(v.w);
    hi[2 * i]     = __nv_bfloat162(hx, hy);
    hi[2 * i + 1] = __nv_bfloat162(hz, hw);
    lo[2 * i]     = __nv_bfloat162(__float2bfloat16(v.x - __bfloat162float(hx)),
                                   __float2bfloat16(v.y - __bfloat162float(hy)));
    lo[2 * i + 1] = __nv_bfloat162(__float2bfloat16(v.z - __bfloat162float(hz)),
                                   __float2bfloat16(v.w - __bfloat162float(hw)));
}

__global__ __launch_bounds__(256) void transpose_split_kernel(
    int K, int N, const float* __restrict__ W,
    __nv_bfloat16* __restrict__ Thi, __nv_bfloat16* __restrict__ Tlo)
{
    __shared__ float t[32][33];
    const int n0 = blockIdx.x * 32, k0 = blockIdx.y * 32;
    const int tx = threadIdx.x, ty = threadIdx.y;   // 32 x 8
#pragma unroll
    for (int j = 0; j < 4; j++) {
        int k = k0 + ty + j * 8;
        t[ty + j * 8][tx] = W[(size_t)k * N + n0 + tx];
    }
    __syncthreads();
#pragma unroll
    for (int j = 0; j < 4; j++) {
        int n = n0 + ty + j * 8;
        int k = k0 + tx;
        float v = t[tx][ty + j * 8];
        __nv_bfloat16 h = __float2bfloat16(v);
        Thi[(size_t)n * K + k] = h;
        Tlo[(size_t)n * K + k] = __float2bfloat16(v - __bfloat162float(h));
    }
}

// ================= mma.sync GEMM: C[M,N] = A[M,K] @ Bt[N,K]^T + bias =========
// mode 0: write fp32 C.  mode 1: GEMM1 epilogue — head-indexed RoPE + split
// bf16 q/k/v stores ([B,H,T,hd] layout).
#define GBK   32
#define PSTR  40
#define PART_SM  (128 * PSTR * 2)
#define STAGE_SM (4 * PART_SM)
#define GEMM_SMEM (2 * STAGE_SM)

__global__ __launch_bounds__(256, 2) void gemm_mma_kernel(
    int K, int N,
    const __nv_bfloat16* __restrict__ Ahi, const __nv_bfloat16* __restrict__ Alo,
    const __nv_bfloat16* __restrict__ Bhi, const __nv_bfloat16* __restrict__ Blo,
    const float* __restrict__ bias, float* __restrict__ C,
    int mode,
    __nv_bfloat16* __restrict__ qhi, __nv_bfloat16* __restrict__ qlo,
    __nv_bfloat16* __restrict__ khi, __nv_bfloat16* __restrict__ klo,
    __nv_bfloat16* __restrict__ vhi, __nv_bfloat16* __restrict__ vlo)
{
    extern __shared__ char smem[];
    const uint32_t smb = smem_u32(smem);
    const int tid = threadIdx.x;
    const int lane = tid & 31;
    const int wid = tid >> 5;
    const int bx = blockIdx.x;
    const int by = blockIdx.y;
    const int wm = wid >> 1;
    const int wn = wid & 1;

    const __nv_bfloat16* src[4];
    src[0] = Ahi + (size_t)by * 128 * K;
    src[1] = Alo + (size_t)by * 128 * K;
    src[2] = Bhi + (size_t)bx * 128 * K;
    src[3] = Blo + (size_t)bx * 128 * K;

    const int lr = tid >> 1;
    const int lu = (tid & 1) * 2;

    float acc[2][8][4];
#pragma unroll
    for (int mt = 0; mt < 2; mt++)
#pragma unroll
        for (int nt = 0; nt < 8; nt++)
#pragma unroll
            for (int j = 0; j < 4; j++) acc[mt][nt][j] = 0.f;

    const int nch = K / GBK;
    {
        const uint32_t sb = smb;
#pragma unroll
        for (int p = 0; p < 4; p++) {
            const char* g = (const char*)(src[p] + (size_t)lr * K);
            uint32_t s = sb + p * PART_SM + lr * 80 + lu * 16;
            cp16(s,      g + lu * 16);
            cp16(s + 16, g + lu * 16 + 16);
        }
        CP_COMMIT();
    }

    for (int ch = 0; ch < nch; ch++) {
        if (ch + 1 < nch) {
            const uint32_t sb = smb + ((ch + 1) & 1) * STAGE_SM;
            const int koff = (ch + 1) * GBK;
#pragma unroll
            for (int p = 0; p < 4; p++) {
                const char* g = (const char*)(src[p] + (size_t)lr * K + koff);
                uint32_t s = sb + p * PART_SM + lr * 80 + lu * 16;
                cp16(s,      g + lu * 16);
                cp16(s + 16, g + lu * 16 + 16);
            }
            CP_COMMIT();
            CP_WAIT_1();
        } else {
            CP_WAIT_0();
        }
        __syncthreads();

        const uint32_t sb = smb + (ch & 1) * STAGE_SM;
#pragma unroll
        for (int ks = 0; ks < 2; ks++) {
            const int kb = ks * 16;
            uint32_t a[2][2][4];
#pragma unroll
            for (int pp = 0; pp < 2; pp++) {
#pragma unroll
                for (int mt = 0; mt < 2; mt++) {
                    int row = wm * 32 + mt * 16 + (lane & 15);
                    int kk  = kb + ((lane >> 4) & 1) * 8;
                    uint32_t ad = sb + pp * PART_SM + row * 80 + kk * 2;
                    LDM_X4(a[pp][mt], ad);
                }
            }
#pragma unroll
            for (int np = 0; np < 4; np++) {
                int rowb = wn * 64 + np * 16 + (lane & 7) + ((lane >> 4) & 1) * 8;
                int kk   = kb + ((lane >> 3) & 1) * 8;
                uint32_t bh[4], bl[4];
                LDM_X4(bh, sb + 2 * PART_SM + rowb * 80 + kk * 2);
                LDM_X4(bl, sb + 3 * PART_SM + rowb * 80 + kk * 2);
#pragma unroll
                for (int half = 0; half < 2; half++)
#pragma unroll
                    for (int mt = 0; mt < 2; mt++)
                        MMA16816(acc[mt][np * 2 + half], a[0][mt],
                                 bh[half * 2], bh[half * 2 + 1]);
#pragma unroll
                for (int half = 0; half < 2; half++)
#pragma unroll
                    for (int mt = 0; mt < 2; mt++)
                        MMA16816(acc[mt][np * 2 + half], a[0][mt],
                                 bl[half * 2], bl[half * 2 + 1]);
#pragma unroll
                for (int half = 0; half < 2; half++)
#pragma unroll
                    for (int mt = 0; mt < 2; mt++)
                        MMA16816(acc[mt][np * 2 + half], a[1][mt],
                                 bh[half * 2], bh[half * 2 + 1]);
            }
        }
        __syncthreads();
    }

    const int gq = lane >> 2;
    const int cn = (lane & 3) * 2;
    if (mode == 0) {
#pragma unroll
        for (int mt = 0; mt < 2; mt++) {
            const int row = by * 128 + wm * 32 + mt * 16 + gq;
#pragma unroll
            for (int nt = 0; nt < 8; nt++) {
                const int col = bx * 128 + wn * 64 + nt * 8 + cn;
                const float2 bb = *(const float2*)(bias + col);
                float2 o0, o1;
                o0.x = acc[mt][nt][0] + bb.x;
                o0.y = acc[mt][nt][1] + bb.y;
                o1.x = acc[mt][nt][2] + bb.x;
                o1.y = acc[mt][nt][3] + bb.y;
                *(float2*)(C + (size_t)row * N + col)       = o0;
                *(float2*)(C + (size_t)(row + 8) * N + col) = o1;
            }
        }
    } else {
        // RoPE + split epilogue (GEMM1). col pair (col, col+1) = rope pair.
#pragma unroll
        for (int nt = 0; nt < 8; nt++) {
            const int col = bx * 128 + wn * 64 + nt * 8 + cn;
            const int p3  = col >> 10;           // 0=q 1=k 2=v
            const int rem = col & 1023;
            const int hh  = rem >> 6;
            const int d   = rem & 63;
            float si = 0.f, co = 1.f;
            if (p3 < 2) {
                const float theta = __powf(10000.0f, -(float)(d >> 1) / 32.0f);
                sincosf((float)hh * theta, &si, &co);
            }
            const float b0 = bias[col], b1 = bias[col + 1];
            __nv_bfloat16* dsthi = (p3 == 0) ? qhi : (p3 == 1) ? khi : vhi;
            __nv_bfloat16* dstlo = (p3 == 0) ? qlo : (p3 == 1) ? klo : vlo;
#pragma unroll
            for (int mt = 0; mt < 2; mt++) {
#pragma unroll
                for (int rr = 0; rr < 2; rr++) {
                    const int mm = by * 128 + wm * 32 + mt * 16 + gq + rr * 8;
                    const int bb = mm >> 11;          // / SEQ
                    const int tt = mm & (SEQ - 1);
                    float v0 = acc[mt][nt][rr * 2 + 0] + b0;
                    float v1 = acc[mt][nt][rr * 2 + 1] + b1;
                    float o0, o1;
                    if (p3 < 2) {
                        o0 = v0 * co - v1 * si;
                        o1 = v1 * co + v0 * si;
                    } else {
                        o0 = v0; o1 = v1;
                    }
                    const size_t off =
                        (((size_t)(bb * NHEAD + hh)) * SEQ + tt) * HD + d;
                    uint32_t hi, lo;
                    split2(o0, o1, hi, lo);
                    *reinterpret_cast<uint32_t*>(dsthi + off) = hi;
                    *reinterpret_cast<uint32_t*>(dstlo + off) = lo;
                }
            }
        }
    }
}

// ---------------- Flash attention (causal), mma.sync bf16 split --------------
// CTA: 128 q rows (8 warps x m16), K/V tiles 64 rows, double-buffered cp.async.
// (R14 configuration — measured best.)
#define AKSTRB 144
#define APART  (64 * AKSTRB)
#define ASTAGE (4 * APART)
#define ATTN_SMEM (2 * ASTAGE)

__global__ __launch_bounds__(256, 1) void attn_mma_kernel(
    const __nv_bfloat16* __restrict__ Qhi, const __nv_bfloat16* __restrict__ Qlo,
    const __nv_bfloat16* __restrict__ Khi, const __nv_bfloat16* __restrict__ Klo,
    const __nv_bfloat16* __restrict__ Vhi, const __nv_bfloat16* __restrict__ Vlo,
    __nv_bfloat16* __restrict__ Yhi, __nv_bfloat16* __restrict__ Ylo)
{
    extern __shared__ char smem[];
    const uint32_t smb = smem_u32(smem);
    const int tid = threadIdx.x, lane = tid & 31, wid = tid >> 5;
    const int qt = blockIdx.x, h = blockIdx.y, b = blockIdx.z;
    const int qbase = qt * 128;
    const size_t headOff = ((size_t)(b * NHEAD + h)) * SEQ * HD;

    // ---- stage Q and load fragments ----
    {
        const int part = tid >> 7;
        const int row  = tid & 127;
        const __nv_bfloat16* gqp = (part == 0 ? Qhi : Qlo) + headOff + (size_t)(qbase + row) * HD;
        uint32_t s = smb + part * 18432 + row * AKSTRB;
#pragma unroll
        for (int u = 0; u < 8; u++) cp16(s + u * 16, (const char*)gqp + u * 16);
        CP_COMMIT();
        CP_WAIT_0();
    }
    __syncthreads();

    uint32_t qh[4][4], ql[4][4];
    {
        const int row = wid * 16 + (lane & 15);
        const int ko  = ((lane >> 4) & 1) * 8;
#pragma unroll
        for (int kb = 0; kb < 4; kb++) {
            uint32_t ad = smb + row * AKSTRB + (kb * 16 + ko) * 2;
            LDM_X4(qh[kb], ad);
            LDM_X4(ql[kb], ad + 18432);
        }
    }
    __syncthreads();

    float m0 = -1e30f, m1 = -1e30f, l0 = 0.f, l1 = 0.f;
    float Oacc[8][4];
#pragma unroll
    for (int nt = 0; nt < 8; nt++)
#pragma unroll
        for (int j = 0; j < 4; j++) Oacc[nt][j] = 0.f;

    const int nkt = 2 * qt + 2;
    const int ldp  = tid >> 6;
    const int ldr  = tid & 63;
    const __nv_bfloat16* ldsrc =
        (ldp == 0 ? Khi : ldp == 1 ? Klo : ldp == 2 ? Vhi : Vlo) + headOff;

    {
        const char* g = (const char*)(ldsrc + (size_t)ldr * HD);
        uint32_t s = smb + ldp * APART + ldr * AKSTRB;
#pragma unroll
        for (int u = 0; u < 8; u++) cp16(s + u * 16, g + u * 16);
        CP_COMMIT();
    }

    const int gq = lane >> 2;
    const int c2 = (lane & 3) * 2;

    for (int kt = 0; kt < nkt; kt++) {
        if (kt + 1 < nkt) {
            const char* g = (const char*)(ldsrc + (size_t)((kt + 1) * 64 + ldr) * HD);
            uint32_t s = smb + ((kt + 1) & 1) * ASTAGE + ldp * APART + ldr * AKSTRB;
#pragma unroll
            for (int u = 0; u < 8; u++) cp16(s + u * 16, g + u * 16);
            CP_COMMIT();
            CP_WAIT_1();
        } else {
            CP_WAIT_0();
        }
        __syncthreads();

        const uint32_t sb = smb + (kt & 1) * ASTAGE;
        const int ktbase = kt * 64;
        if (ktbase <= qbase + wid * 16 + 15) {
            float acc[8][4];
#pragma unroll
            for (int nt = 0; nt < 8; nt++)
#pragma unroll
                for (int j = 0; j < 4; j++) acc[nt][j] = 0.f;

#pragma unroll
            for (int kb = 0; kb < 4; kb++) {
                const int kcol = kb * 16 + ((lane >> 3) & 1) * 8;
#pragma unroll
                for (int npp = 0; npp < 2; npp++) {
                    const int nr0 = (npp * 2) * 16 + (lane & 7) + ((lane >> 4) & 1) * 8;
                    const int nr1 = (npp * 2 + 1) * 16 + (lane & 7) + ((lane >> 4) & 1) * 8;
                    uint32_t kh0[4], kl0[4], kh1[4], kl1[4];
                    const uint32_t ad0 = sb + nr0 * AKSTRB + kcol * 2;
                    const uint32_t ad1 = sb + nr1 * AKSTRB + kcol * 2;
                    LDM_X4(kh0, ad0);
                    LDM_X4(kl0, ad0 + APART);
                    LDM_X4(kh1, ad1);
                    LDM_X4(kl1, ad1 + APART);
                    const int t0 = npp * 4;
                    MMA16816(acc[t0 + 0], qh[kb], kh0[0], kh0[1]);
                    MMA16816(acc[t0 + 1], qh[kb], kh0[2], kh0[3]);
                    MMA16816(acc[t0 + 2], qh[kb], kh1[0], kh1[1]);
                    MMA16816(acc[t0 + 3], qh[kb], kh1[2], kh1[3]);
                    MMA16816(acc[t0 + 0], qh[kb], kl0[0], kl0[1]);
                    MMA16816(acc[t0 + 1], qh[kb], kl0[2], kl0[3]);
                    MMA16816(acc[t0 + 2], qh[kb], kl1[0], kl1[1]);
                    MMA16816(acc[t0 + 3], qh[kb], kl1[2], kl1[3]);
                    MMA16816(acc[t0 + 0], ql[kb], kh0[0], kh0[1]);
                    MMA16816(acc[t0 + 1], ql[kb], kh0[2], kh0[3]);
                    MMA16816(acc[t0 + 2], ql[kb], kh1[0], kh1[1]);
                    MMA16816(acc[t0 + 3], ql[kb], kh1[2], kh1[3]);
                }
            }

            const int row0 = qbase + wid * 16 + gq;
            const int row1 = row0 + 8;
            if (ktbase + 63 > qbase + wid * 16) {
#pragma unroll
                for (int nt = 0; nt < 8; nt++) {
#pragma unroll
                    for (int j = 0; j < 4; j++) {
                        const int col = ktbase + nt * 8 + c2 + (j & 1);
                        const int r   = (j < 2) ? row0 : row1;
                        float sv = acc[nt][j] * 0.125f;
                        if (col > r) sv = -1e30f;
                        acc[nt][j] = sv;
                    }
                }
            } else {
#pragma unroll
                for (int nt = 0; nt < 8; nt++)
#pragma unroll
                    for (int j = 0; j < 4; j++) acc[nt][j] *= 0.125f;
            }

            float mx0 = -1e30f, mx1 = -1e30f;
#pragma unroll
            for (int nt = 0; nt < 8; nt++) {
                mx0 = fmaxf(mx0, fmaxf(acc[nt][0], acc[nt][1]));
                mx1 = fmaxf(mx1, fmaxf(acc[nt][2], acc[nt][3]));
            }
            mx0 = fmaxf(mx0, __shfl_xor_sync(0xffffffffu, mx0, 1));
            mx0 = fmaxf(mx0, __shfl_xor_sync(0xffffffffu, mx0, 2));
            mx1 = fmaxf(mx1, __shfl_xor_sync(0xffffffffu, mx1, 1));
            mx1 = fmaxf(mx1, __shfl_xor_sync(0xffffffffu, mx1, 2));

            const float mn0 = fmaxf(m0, mx0), mn1 = fmaxf(m1, mx1);
            const float al0 = __expf(m0 - mn0), al1 = __expf(m1 - mn1);
            float s0 = 0.f, s1 = 0.f;
#pragma unroll
            for (int nt = 0; nt < 8; nt++) {
                float p0 = __expf(acc[nt][0] - mn0);
                float p1 = __expf(acc[nt][1] - mn0);
                float p2 = __expf(acc[nt][2] - mn1);
                float p3 = __expf(acc[nt][3] - mn1);
                acc[nt][0] = p0; acc[nt][1] = p1; acc[nt][2] = p2; acc[nt][3] = p3;
                s0 += p0 + p1;
                s1 += p2 + p3;
            }
            s0 += __shfl_xor_sync(0xffffffffu, s0, 1);
            s0 += __shfl_xor_sync(0xffffffffu, s0, 2);
            s1 += __shfl_xor_sync(0xffffffffu, s1, 1);
            s1 += __shfl_xor_sync(0xffffffffu, s1, 2);
            l0 = l0 * al0 + s0;
            l1 = l1 * al1 + s1;
            m0 = mn0; m1 = mn1;
#pragma unroll
            for (int nt = 0; nt < 8; nt++) {
                Oacc[nt][0] *= al0; Oacc[nt][1] *= al0;
                Oacc[nt][2] *= al1; Oacc[nt][3] *= al1;
            }

#pragma unroll
            for (int kb = 0; kb < 4; kb++) {
                uint32_t ph[4], pl[4];
                split2(acc[2 * kb][0],     acc[2 * kb][1],     ph[0], pl[0]);
                split2(acc[2 * kb][2],     acc[2 * kb][3],     ph[1], pl[1]);
                split2(acc[2 * kb + 1][0], acc[2 * kb + 1][1], ph[2], pl[2]);
                split2(acc[2 * kb + 1][2], acc[2 * kb + 1][3], ph[3], pl[3]);
                const int krow = kb * 16 + (lane & 7) + ((lane >> 3) & 1) * 8;
#pragma unroll
                for (int npp = 0; npp < 2; npp++) {
                    const int nc0 = (npp * 2) * 16 + ((lane >> 4) & 1) * 8;
                    const int nc1 = (npp * 2 + 1) * 16 + ((lane >> 4) & 1) * 8;
                    uint32_t vh0[4], vl0[4], vh1[4], vl1[4];
                    const uint32_t ad0 = sb + 2 * APART + krow * AKSTRB + nc0 * 2;
                    const uint32_t ad1 = sb + 2 * APART + krow * AKSTRB + nc1 * 2;
                    LDM_X4_T(vh0, ad0);
                    LDM_X4_T(vl0, ad0 + APART);
                    LDM_X4_T(vh1, ad1);
                    LDM_X4_T(vl1, ad1 + APART);
                    const int t0 = npp * 4;
                    MMA16816(Oacc[t0 + 0], ph, vh0[0], vh0[1]);
                    MMA16816(Oacc[t0 + 1], ph, vh0[2], vh0[3]);
                    MMA16816(Oacc[t0 + 2], ph, vh1[0], vh1[1]);
                    MMA16816(Oacc[t0 + 3], ph, vh1[2], vh1[3]);
                    MMA16816(Oacc[t0 + 0], ph, vl0[0], vl0[1]);
                    MMA16816(Oacc[t0 + 1], ph, vl0[2], vl0[3]);
                    MMA16816(Oacc[t0 + 2], ph, vl1[0], vl1[1]);
                    MMA16816(Oacc[t0 + 3], ph, vl1[2], vl1[3]);
                    MMA16816(Oacc[t0 + 0], pl, vh0[0], vh0[1]);
                    MMA16816(Oacc[t0 + 1], pl, vh0[2], vh0[3]);
                    MMA16816(Oacc[t0 + 2], pl, vh1[0], vh1[1]);
                    MMA16816(Oacc[t0 + 3], pl, vh1[2], vh1[3]);
                }
            }
        }
        __syncthreads();
    }

    // ---- epilogue: normalize, split to bf16 hi/lo, store into GEMM2 A-layout -
    const float inv0 = 1.0f / l0, inv1 = 1.0f / l1;
    const int r0 = qbase + wid * 16 + gq;
    const size_t m0r = (size_t)b * SEQ + r0;
    const size_t m1r = m0r + 8;
    const int colb = h * HD + c2;
#pragma unroll
    for (int nt = 0; nt < 8; nt++) {
        uint32_t hi0, lo0, hi1, lo1;
        split2(Oacc[nt][0] * inv0, Oacc[nt][1] * inv0, hi0, lo0);
        split2(Oacc[nt][2] * inv1, Oacc[nt][3] * inv1, hi1, lo1);
        const size_t o0 = m0r * CDIM + colb + nt * 8;
        const size_t o1 = m1r * CDIM + colb + nt * 8;
        *reinterpret_cast<uint32_t*>(Yhi + o0) = hi0;
        *reinterpret_cast<uint32_t*>(Ylo + o0) = lo0;
        *reinterpret_cast<uint32_t*>(Yhi + o1) = hi1;
        *reinterpret_cast<uint32_t*>(Ylo + o1) = lo1;
    }
}

// ---------------- launch ----------------------------------------------------
extern "C" void kernel_launch(void* const* d_in, const int* in_sizes, int n_in,
                              void* d_out, int out_size)
{
    const float* x      = (const float*)d_in[0];
    const float* W_attn = (const float*)d_in[1];
    const float* b_attn = (const float*)d_in[2];
    const float* W_proj = (const float*)d_in[3];
    const float* b_proj = (const float*)d_in[4];
    float* out = (float*)d_out;

    __nv_bfloat16 *ahi, *alo, *w1hi, *w1lo, *w2hi, *w2lo;
    __nv_bfloat16 *qhi, *qlo, *khi, *klo, *vhi, *vlo;
    cudaGetSymbolAddress((void**)&ahi,  g_ahi);
    cudaGetSymbolAddress((void**)&alo,  g_alo);
    cudaGetSymbolAddress((void**)&w1hi, g_w1hi);
    cudaGetSymbolAddress((void**)&w1lo, g_w1lo);
    cudaGetSymbolAddress((void**)&w2hi, g_w2hi);
    cudaGetSymbolAddress((void**)&w2lo, g_w2lo);
    cudaGetSymbolAddress((void**)&qhi,  g_qhi);
    cudaGetSymbolAddress((void**)&qlo,  g_qlo);
    cudaGetSymbolAddress((void**)&khi,  g_khi);
    cudaGetSymbolAddress((void**)&klo,  g_klo);
    cudaGetSymbolAddress((void**)&vhi,  g_vhi);
    cudaGetSymbolAddress((void**)&vlo,  g_vlo);

    cudaFuncSetAttribute(gemm_mma_kernel,
                         cudaFuncAttributeMaxDynamicSharedMemorySize, GEMM_SMEM);
    cudaFuncSetAttribute(attn_mma_kernel,
                         cudaFuncAttributeMaxDynamicSharedMemorySize, ATTN_SMEM);

    // convert weights (transpose + split)
    {
        dim3 blk(32, 8);
        dim3 g1(C3 / 32, CDIM / 32);
        transpose_split_kernel<<<g1, blk>>>(CDIM, C3, W_attn, w1hi, w1lo);
        dim3 g2(CDIM / 32, CDIM / 32);
        transpose_split_kernel<<<g2, blk>>>(CDIM, CDIM, W_proj, w2hi, w2lo);
    }
    // convert x
    {
        int total4 = MROWS * CDIM / 4;
        convert_split_kernel<<<(total4 + 255) / 256, 256>>>(
            total4, (const float4*)x, (__nv_bfloat162*)ahi, (__nv_bfloat162*)alo);
    }
    // GEMM1 (fused RoPE + split epilogue): q/k/v <- rope(x @ W_attn + b_attn)
    {
        dim3 grid(C3 / 128, MROWS / 128);
        gemm_mma_kernel<<<grid, 256, GEMM_SMEM>>>(CDIM, C3,
                                                  ahi, alo, w1hi, w1lo, b_attn,
                                                  nullptr, 1,
                                                  qhi, qlo, khi, klo, vhi, vlo);
    }
    // Flash attention (tensor cores), 128-row CTAs (R14 best config)
    {
        dim3 grid(SEQ / 128, NHEAD, BATCH);
        attn_mma_kernel<<<grid, 256, ATTN_SMEM>>>(qhi, qlo, khi, klo, vhi, vlo,
                                                  ahi, alo);
    }
    // GEMM2: out = y @ W_proj + b_proj
    {
        dim3 grid(CDIM / 128, MROWS / 128);
        gemm_mma_kernel<<<grid, 256, GEMM_SMEM>>>(CDIM, CDIM,
                                                  ahi, alo, w2hi, w2lo, b_proj,
                                                  out, 0,
                                                  nullptr, nullptr, nullptr,
                                                  nullptr, nullptr, nullptr);
    }
}